// round 17
// baseline (speedup 1.0000x reference)
#include <cuda_runtime.h>
#include <math.h>
#include <stdint.h>

// ---------------------------------------------------------------------------
// DCRNN encoder, TF32 mma.sync, Chebyshev-collapsed diffusion.
// Round 13: round-8 GEMM config (64x32 warp tile, 256 thr) + pre-permuted
// S/M2 in mma-fragment order (tf32 pre-applied) -> A fragment = 1x LDS.128,
// cp.async A staging, zero cvts in the diffusion inner loop.
// x1 = S@x ; x2 = (2S^2 - I)@x = M2@x (M2 precomputed fp32).
// Layout [N, B, F]: diffusion = A[512,512] @ X[512,4096].
// ---------------------------------------------------------------------------

namespace {
constexpr int TT = 32, BB = 32, NN = 512, HH = 128, LL = 2;
constexpr long NBH  = (long)NN * BB * HH;       // 2,097,152
constexpr long TNBH = (long)TT * NBH;
constexpr long TNBG = (long)TT * NN * BB * 256;
}

// Scratch
__device__ float g_X0[TNBH];
__device__ float g_Xn[TNBH];
__device__ float g_X1[TNBH];
__device__ float g_X2[TNBH];
__device__ float g_GXg[TNBG];
__device__ float g_GXc[TNBH];
__device__ float g_H0[NBH];
__device__ float g_H1[NBH];
__device__ float g_H2[NBH];
__device__ float g_RH0[NBH];
__device__ float g_RH1[NBH];
__device__ float g_RH2[NBH];
__device__ float g_U[NBH];
__device__ float g_M2[512 * 512];
__device__ float g_SP[512 * 512];    // S  permuted to fragment order (tf32)
__device__ float g_M2P[512 * 512];   // M2 permuted to fragment order (tf32)
__device__ float g_WgT[(long)LL * 256 * 768];   // [L][256][768]
__device__ float g_WcT[(long)LL * 128 * 768];   // [L][128][768]

// ---------------------------------------------------------------------------
__device__ __forceinline__ float tf32r(float x) {
    uint32_t u; asm("cvt.rna.tf32.f32 %0, %1;" : "=r"(u) : "f"(x));
    return __uint_as_float(u);
}
__device__ __forceinline__ float4 tf4(float4 v) {
    return make_float4(tf32r(v.x), tf32r(v.y), tf32r(v.z), tf32r(v.w));
}
__device__ __forceinline__ void mma_tf32(float* d, const uint32_t* a, const uint32_t* b) {
    asm volatile(
        "mma.sync.aligned.m16n8k8.row.col.f32.tf32.tf32.f32 "
        "{%0,%1,%2,%3}, {%4,%5,%6,%7}, {%8,%9}, {%0,%1,%2,%3};\n"
        : "+f"(d[0]), "+f"(d[1]), "+f"(d[2]), "+f"(d[3])
        : "r"(a[0]), "r"(a[1]), "r"(a[2]), "r"(a[3]), "r"(b[0]), "r"(b[1]));
}
__device__ __forceinline__ uint32_t smem_u32(const void* p) {
    uint32_t a;
    asm("{ .reg .u64 t; cvta.to.shared.u64 t, %1; cvt.u32.u64 %0, t; }" : "=r"(a) : "l"(p));
    return a;
}
__device__ __forceinline__ void cpa16(uint32_t saddr, const void* g) {
    asm volatile("cp.async.ca.shared.global [%0], [%1], 16;" :: "r"(saddr), "l"(g));
}
#define CPA_COMMIT() asm volatile("cp.async.commit_group;")
#define CPA_WAIT0()  asm volatile("cp.async.wait_group 0;")

// ---------------------------------------------------------------------------
// M2 = 2*S@S - I, fp32
__global__ void sq_k(const float* __restrict__ S, float* __restrict__ M2) {
    __shared__ float As[32][33];
    __shared__ float Bs[32][33];
    int tx = threadIdx.x, ty = threadIdx.y;
    int row = (blockIdx.y << 5) + ty, col = (blockIdx.x << 5) + tx;
    float acc = 0.f;
    for (int k0 = 0; k0 < 512; k0 += 32) {
        As[ty][tx] = S[(long)row * 512 + k0 + tx];
        Bs[ty][tx] = S[(long)(k0 + ty) * 512 + col];
        __syncthreads();
#pragma unroll
        for (int kk = 0; kk < 32; kk++) acc += As[ty][kk] * Bs[kk][tx];
        __syncthreads();
    }
    M2[(long)row * 512 + col] = 2.f * acc - (row == col ? 1.f : 0.f);
}

// Permute A[512][512] -> AP[mb16][kb8][lane][4], tf32 pre-applied.
// Fragment reg order: j=0:(r,c) j=1:(r+8,c) j=2:(r,c+4) j=3:(r+8,c+4)
__global__ void perm_a_k(const float* __restrict__ A, float* __restrict__ AP) {
    int idx = blockIdx.x * blockDim.x + threadIdx.x;   // 262144
    int j = idx & 3;
    int lane = (idx >> 2) & 31;
    int kb = (idx >> 7) & 63;
    int mb = idx >> 13;
    int r = lane >> 2, c = lane & 3;
    int row = mb * 16 + r + (j & 1) * 8;
    int col = kb * 8 + c + ((j >> 1) << 2);
    AP[idx] = tf32r(A[(long)row * 512 + col]);
}

// transpose inputs [T,B,N,D] -> [T,N,B,D]
__global__ void transpose_in_k(const float4* __restrict__ in, float4* __restrict__ out) {
    long idx = (long)blockIdx.x * blockDim.x + threadIdx.x;
    int d4 = (int)(idx & 31);
    long rr = idx >> 5;
    int b = (int)(rr & 31); rr >>= 5;
    int n = (int)(rr & 511); rr >>= 9;
    int t = (int)rr;
    out[idx] = in[((((long)t * BB + b) * NN + n) << 5) + d4];
}

// transpose hidden [B,N,H] -> [N,B,H]
__global__ void transpose_h_k(const float4* __restrict__ in, float4* __restrict__ out) {
    long idx = (long)blockIdx.x * blockDim.x + threadIdx.x;
    int d4 = (int)(idx & 31);
    int b  = (int)((idx >> 5) & 31);
    int n  = (int)(idx >> 10);
    out[idx] = in[(((long)b * NN + n) << 5) + d4];
}

// all 4 weight transposes in one kernel: W [768,O] -> WT [O,768]
__global__ void transpose_w_all(const float* __restrict__ Wg, const float* __restrict__ Wc,
                                float* __restrict__ WgT, float* __restrict__ WcT) {
    int idx = blockIdx.x * blockDim.x + threadIdx.x;
    const int NG = 2 * 768 * 256;
    const int NCt = 2 * 768 * 128;
    if (idx < NG) {
        int l = idx / (768 * 256), r = idx % (768 * 256);
        int f = r / 256, o = r % 256;
        WgT[(long)l * 256 * 768 + (long)o * 768 + f] = Wg[(long)l * 768 * 256 + (long)f * 256 + o];
    } else if (idx < NG + NCt) {
        int j = idx - NG;
        int l = j / (768 * 128), r = j % (768 * 128);
        int f = r / 128, o = r % 128;
        WcT[(long)l * 128 * 768 + (long)o * 768 + f] = Wc[(long)l * 768 * 128 + (long)f * 128 + o];
    }
}

// ---------------------------------------------------------------------------
// Batched diffusion GEMM (TF32): z = 2*pair + which:
//   C_which[pair] = (which ? M2 : S) @ B[pair]     B: [512, 4096]
// CTA 128x128, 256 threads, 8 warps of 64x32 (round-8 config).
// A from pre-permuted fragment layout via cp.async; B register-staged w/ cvt.
__global__ __launch_bounds__(256, 2) void gemm_diff2(
    const float* __restrict__ SP, const float* __restrict__ M2P,
    const float* __restrict__ Bbase, long bStride,
    float* __restrict__ C1, float* __restrict__ C2, long cStride)
{
    constexpr int NC = 4096;
    const int pair = blockIdx.z >> 1, which = blockIdx.z & 1;
    const float* AP = which ? M2P : SP;
    const float* Bp = Bbase + (long)pair * bStride;
    float* Cp = (which ? C2 : C1) + (long)pair * cStride;

    __shared__ float APs[2][2048];     // [stage][mbl(8)][kbl(2)][lane(32)][4]
    __shared__ float Bs[2][16][136];   // [stage][k][n]
    const uint32_t sA = smem_u32(APs);

    const int tid = threadIdx.x;
    const int lane = tid & 31, warp = tid >> 5;
    const int wm0 = (warp & 1) << 6;       // 0/64
    const int wn0 = (warp >> 1) << 5;      // 0..96
    const int r = lane >> 2, c = lane & 3;
    const int m0 = blockIdx.y << 7, n0 = blockIdx.x << 7;
    const int mb0 = m0 >> 4;

    const int b_k  = tid >> 4;             // k 0..15
    const int b_n4 = (tid & 15) << 2;      // n 0..60 step 4

    float acc[4][4][4] = {};
    float4 rb0, rb1;

    auto loadB = [&](int kt) {
        const float* bp = Bp + (long)((kt << 4) + b_k) * NC + n0 + b_n4;
        rb0 = *(const float4*)(bp);
        rb1 = *(const float4*)(bp + 64);
    };
    auto storeB = [&](int s) {
        *(float4*)&Bs[s][b_k][b_n4]      = tf4(rb0);
        *(float4*)&Bs[s][b_k][b_n4 + 64] = tf4(rb1);
    };
    auto cpaA = [&](int kt, int s) {
#pragma unroll
        for (int h = 0; h < 2; h++) {
            int q = tid + h * 256;
            int mbl = q >> 6, rem = q & 63;
            int kb = (kt << 1) + (rem >> 5), ch = rem & 31;
            const float* g = AP + (((long)(mb0 + mbl) * 64 + kb) << 7) + (ch << 2);
            cpa16(sA + (uint32_t)((s * 2048 + q * 4) << 2), g);
        }
    };

    loadB(0); cpaA(0, 0); CPA_COMMIT();
    storeB(0); CPA_WAIT0(); __syncthreads();
    int cur = 0;
    for (int kt = 0; kt < 32; kt++) {
        const bool more = (kt + 1 < 32);
        if (more) { loadB(kt + 1); cpaA(kt + 1, cur ^ 1); CPA_COMMIT(); }
#pragma unroll
        for (int kk = 0; kk < 16; kk += 8) {
            const int kbl = kk >> 3;
            uint32_t af[4][4], bf[4][2];
#pragma unroll
            for (int mi = 0; mi < 4; mi++) {
                int mbl = ((warp & 1) << 2) + mi;
                const uint4 a4 = *(const uint4*)&APs[cur][((mbl * 2 + kbl) * 32 + lane) * 4];
                af[mi][0] = a4.x; af[mi][1] = a4.y; af[mi][2] = a4.z; af[mi][3] = a4.w;
            }
#pragma unroll
            for (int ni = 0; ni < 4; ni++) {
                int nn = wn0 + ni * 8 + r;
                bf[ni][0] = __float_as_uint(Bs[cur][kk + c][nn]);
                bf[ni][1] = __float_as_uint(Bs[cur][kk + c + 4][nn]);
            }
#pragma unroll
            for (int mi = 0; mi < 4; mi++)
#pragma unroll
                for (int ni = 0; ni < 4; ni++)
                    mma_tf32(acc[mi][ni], af[mi], bf[ni]);
        }
        if (more) { storeB(cur ^ 1); CPA_WAIT0(); }
        __syncthreads();
        cur ^= 1;
    }
#pragma unroll
    for (int mi = 0; mi < 4; mi++) {
        int row = m0 + wm0 + mi * 16 + r;
#pragma unroll
        for (int ni = 0; ni < 4; ni++) {
            int col = n0 + wn0 + ni * 8 + 2 * c;
            const float* ap = acc[mi][ni];
            long o0 = (long)row * NC + col, o1 = o0 + 8L * NC;
            float2 q0, q1;
            q0.x = ap[0]; q0.y = ap[1]; q1.x = ap[2]; q1.y = ap[3];
            *(float2*)(Cp + o0) = q0;
            *(float2*)(Cp + o1) = q1;
        }
    }
}

// ---------------------------------------------------------------------------
// Projection GEMM (TF32), round-8 version.
// D = f( sum_seg A_seg @ WT_seg^T + pre + bias )
// A segs: [M,128]. WT: [O,768]; seg s uses cols s*256+xh_off+0..127.
// modes: 0 plain(+bias)->outC; 1 gates; 2 candidate + GRU update + scatter.
__global__ __launch_bounds__(256, 2) void gemm_proj_t(
    const float* __restrict__ A0, const float* __restrict__ A1, const float* __restrict__ A2,
    const float* __restrict__ WT, int xh_off, int nout,
    const float* __restrict__ pre, const float* __restrict__ bias,
    float* __restrict__ outC, int mode,
    const float* __restrict__ h0c, float* __restrict__ rh0, float* __restrict__ uarr,
    float* __restrict__ h0w, float* __restrict__ out_nbh, float* __restrict__ out_bnh,
    float* __restrict__ finp, int t)
{
    __shared__ float As[2][128][20];   // [stage][m][k]
    __shared__ float Bs[2][16][136];   // [stage][k][n]

    const int tid = threadIdx.x;
    const int lane = tid & 31, warp = tid >> 5;
    const int wm0 = (warp & 1) << 6;
    const int wn0 = (warp >> 1) << 5;
    const int r = lane >> 2, c = lane & 3;
    const int m0 = blockIdx.y << 7, n0 = blockIdx.x << 7;

    const int a_row = tid >> 1;            // m
    const int a_q   = (tid & 1) << 3;      // k 0/8
    const int b_row = tid >> 1;            // n = WT row
    const int b_q   = (tid & 1) << 3;      // k 0/8

    const float* Aseg[3] = {A0, A1, A2};

    float acc[4][4][4] = {};
    float4 ra0, ra1, rb0, rb1;

    auto load_regs = [&](int k0) {
        int seg = k0 >> 7, within = k0 & 127;
        const float* ap = Aseg[seg] + (long)(m0 + a_row) * 128 + within + a_q;
        ra0 = *(const float4*)(ap);
        ra1 = *(const float4*)(ap + 4);
        const float* bp = WT + (long)(n0 + b_row) * 768 + seg * 256 + xh_off + within + b_q;
        rb0 = *(const float4*)(bp);
        rb1 = *(const float4*)(bp + 4);
    };
    auto store_smem = [&](int s) {
        *(float4*)&As[s][a_row][a_q]     = tf4(ra0);
        *(float4*)&As[s][a_row][a_q + 4] = tf4(ra1);
        Bs[s][b_q + 0][b_row] = tf32r(rb0.x); Bs[s][b_q + 1][b_row] = tf32r(rb0.y);
        Bs[s][b_q + 2][b_row] = tf32r(rb0.z); Bs[s][b_q + 3][b_row] = tf32r(rb0.w);
        Bs[s][b_q + 4][b_row] = tf32r(rb1.x); Bs[s][b_q + 5][b_row] = tf32r(rb1.y);
        Bs[s][b_q + 6][b_row] = tf32r(rb1.z); Bs[s][b_q + 7][b_row] = tf32r(rb1.w);
    };

    load_regs(0); store_smem(0); __syncthreads();
    int cur = 0;
    for (int k0 = 0; k0 < 384; k0 += 16) {
        const bool more = (k0 + 16 < 384);
        if (more) load_regs(k0 + 16);
#pragma unroll
        for (int kk = 0; kk < 16; kk += 8) {
            uint32_t af[4][4], bf[4][2];
#pragma unroll
            for (int mi = 0; mi < 4; mi++) {
                int mm = wm0 + mi * 16 + r;
                af[mi][0] = __float_as_uint(As[cur][mm][kk + c]);
                af[mi][1] = __float_as_uint(As[cur][mm + 8][kk + c]);
                af[mi][2] = __float_as_uint(As[cur][mm][kk + c + 4]);
                af[mi][3] = __float_as_uint(As[cur][mm + 8][kk + c + 4]);
            }
#pragma unroll
            for (int ni = 0; ni < 4; ni++) {
                int nn = wn0 + ni * 8 + r;
                bf[ni][0] = __float_as_uint(Bs[cur][kk + c][nn]);
                bf[ni][1] = __float_as_uint(Bs[cur][kk + c + 4][nn]);
            }
#pragma unroll
            for (int mi = 0; mi < 4; mi++)
#pragma unroll
                for (int ni = 0; ni < 4; ni++)
                    mma_tf32(acc[mi][ni], af[mi], bf[ni]);
        }
        if (more) store_smem(cur ^ 1);
        __syncthreads();
        cur ^= 1;
    }

#pragma unroll
    for (int mi = 0; mi < 4; mi++) {
#pragma unroll
        for (int ni = 0; ni < 4; ni++) {
            const float* ap = acc[mi][ni];
#pragma unroll
            for (int half = 0; half < 2; half++) {
                int row = m0 + wm0 + mi * 16 + r + half * 8;
                float v0 = ap[half * 2 + 0];
                float v1 = ap[half * 2 + 1];
                int col = n0 + wn0 + ni * 8 + 2 * c;
                if (mode == 0) {
                    if (bias) { v0 += bias[col]; v1 += bias[col + 1]; }
                    float2 o; o.x = v0; o.y = v1;
                    *(float2*)(outC + (long)row * nout + col) = o;
                } else if (mode == 1) {
                    const float* pp = pre + (long)row * 256 + col;
                    v0 += pp[0]; v1 += pp[1];
                    float g0 = 1.f / (1.f + __expf(-v0));
                    float g1 = 1.f / (1.f + __expf(-v1));
                    if (col < 128) {
                        long o = (long)row * 128 + col;
                        float2 h = *(const float2*)(h0c + o);
                        float2 out; out.x = g0 * h.x; out.y = g1 * h.y;
                        *(float2*)(rh0 + o) = out;
                    } else {
                        long o = (long)row * 128 + (col - 128);
                        float2 out; out.x = g0; out.y = g1;
                        *(float2*)(uarr + o) = out;
                    }
                } else {
                    long o = (long)row * 128 + col;
                    const float* pp = pre + o;
                    v0 += pp[0]; v1 += pp[1];
                    float c0 = tanhf(v0), c1 = tanhf(v1);
                    float2 uu = *(const float2*)(uarr + o);
                    float2 hh = *(const float2*)(h0c + o);
                    float hn0 = uu.x * hh.x + (1.f - uu.x) * c0;
                    float hn1 = uu.y * hh.y + (1.f - uu.y) * c1;
                    float2 out; out.x = hn0; out.y = hn1;
                    *(float2*)(h0w + o) = out;
                    if (out_nbh) *(float2*)(out_nbh + o) = out;
                    int nn2 = row >> 5, bb2 = row & 31;
                    if (out_bnh)
                        *(float2*)(out_bnh + ((((long)t * BB + bb2) * NN + nn2) * HH + col)) = out;
                    if (finp)
                        *(float2*)(finp + (((long)bb2 * NN + nn2) * HH + col)) = out;
                }
            }
        }
    }
}

// ---------------------------------------------------------------------------
extern "C" void kernel_launch(void* const* d_in, const int* in_sizes, int n_in,
                              void* d_out, int out_size) {
    (void)in_sizes; (void)n_in; (void)out_size;
    const float* inputs = (const float*)d_in[0];
    const float* ih     = (const float*)d_in[1];
    const float* S      = (const float*)d_in[2];
    const float* Wg     = (const float*)d_in[3];
    const float* bg     = (const float*)d_in[4];
    const float* Wc     = (const float*)d_in[5];
    const float* bc     = (const float*)d_in[6];
    float* fin    = (float*)d_out;
    float* outcur = fin + (long)LL * BB * NN * HH;

    float *pX0, *pXn, *pX1, *pX2, *pGXg, *pGXc;
    float *pH0, *pH1, *pH2, *pRH0, *pRH1, *pRH2, *pU;
    float *pM2, *pSP, *pM2P, *pWgT, *pWcT;
    cudaGetSymbolAddress((void**)&pX0, g_X0);
    cudaGetSymbolAddress((void**)&pXn, g_Xn);
    cudaGetSymbolAddress((void**)&pX1, g_X1);
    cudaGetSymbolAddress((void**)&pX2, g_X2);
    cudaGetSymbolAddress((void**)&pGXg, g_GXg);
    cudaGetSymbolAddress((void**)&pGXc, g_GXc);
    cudaGetSymbolAddress((void**)&pH0, g_H0);
    cudaGetSymbolAddress((void**)&pH1, g_H1);
    cudaGetSymbolAddress((void**)&pH2, g_H2);
    cudaGetSymbolAddress((void**)&pRH0, g_RH0);
    cudaGetSymbolAddress((void**)&pRH1, g_RH1);
    cudaGetSymbolAddress((void**)&pRH2, g_RH2);
    cudaGetSymbolAddress((void**)&pU, g_U);
    cudaGetSymbolAddress((void**)&pM2, g_M2);
    cudaGetSymbolAddress((void**)&pSP, g_SP);
    cudaGetSymbolAddress((void**)&pM2P, g_M2P);
    cudaGetSymbolAddress((void**)&pWgT, g_WgT);
    cudaGetSymbolAddress((void**)&pWcT, g_WcT);

    // One-time prep
    sq_k<<<dim3(16, 16), dim3(32, 32)>>>(S, pM2);
    perm_a_k<<<1024, 256>>>(S, pSP);
    perm_a_k<<<1024, 256>>>(pM2, pM2P);
    transpose_in_k<<<65536, 256>>>((const float4*)inputs, (float4*)pX0);
    transpose_w_all<<<2304, 256>>>(Wg, Wc, pWgT, pWcT);

    for (int l = 0; l < LL; l++) {
        const float* Xin = (l == 0) ? pX0 : pXn;
        const float* wgt = pWgT + (long)l * 256 * 768;
        const float* wct = pWcT + (long)l * 128 * 768;

        // --- parallel precompute of x-contributions (all T, both diffusion terms) ---
        gemm_diff2<<<dim3(32, 4, 2 * TT), 256>>>(pSP, pM2P, Xin, NBH, pX1, pX2, NBH);
        gemm_proj_t<<<dim3(2, 4096), 256>>>(Xin, pX1, pX2, wgt, 0, 256,
            nullptr, bg + l * 256, pGXg, 0,
            nullptr, nullptr, nullptr, nullptr, nullptr, nullptr, nullptr, 0);
        gemm_proj_t<<<dim3(1, 4096), 256>>>(Xin, pX1, pX2, wct, 0, 128,
            nullptr, bc + l * 128, pGXc, 0,
            nullptr, nullptr, nullptr, nullptr, nullptr, nullptr, nullptr, 0);

        transpose_h_k<<<2048, 256>>>((const float4*)(ih + (long)l * BB * NN * HH), (float4*)pH0);

        // --- sequential recurrence: 4 dependent kernels per step ---
        for (int t = 0; t < TT; t++) {
            gemm_diff2<<<dim3(32, 4, 2), 256>>>(pSP, pM2P, pH0, 0, pH1, pH2, 0);
            gemm_proj_t<<<dim3(2, 128), 256>>>(pH0, pH1, pH2, wgt, 128, 256,
                pGXg + (long)t * NN * BB * 256, nullptr, nullptr, 1,
                pH0, pRH0, pU, nullptr, nullptr, nullptr, nullptr, 0);
            gemm_diff2<<<dim3(32, 4, 2), 256>>>(pSP, pM2P, pRH0, 0, pRH1, pRH2, 0);
            gemm_proj_t<<<dim3(1, 128), 256>>>(pRH0, pRH1, pRH2, wct, 128, 128,
                pGXc + (long)t * NN * BB * 128, nullptr, nullptr, 2,
                pH0, nullptr, pU, pH0,
                (l == 0) ? (pXn + (long)t * NBH) : nullptr,
                (l == 1) ? outcur : nullptr,
                (t == TT - 1) ? (fin + (long)l * BB * NN * HH) : nullptr, t);
        }
    }
}